// round 1
// baseline (speedup 1.0000x reference)
#include <cuda_runtime.h>

#define BATCH 8
#define INPUT_SIZE 8192
#define HIDDEN_SIZE 8192
#define OUTPUT_SIZE 2048
#define KDIM (INPUT_SIZE + HIDDEN_SIZE)   // 16384

// Intermediate hidden activations (8 x 8192 fp32 = 256 KB), allocation-free scratch.
__device__ float g_hidden[BATCH * HIDDEN_SIZE];

// ---------------------------------------------------------------------------
// Kernel 1: pre[b,h] = x[b,:]·W[h,0:8192] + h0[b,:]·W[h,8192:16384] + bias[h]
//           hidden[b,h] = tanh(pre)
// Block: 256 threads (8 warps), 4 rows per warp -> 32 rows per block.
// K is tiled in chunks of 1024 floats staged in shared memory (8 batches).
// ---------------------------------------------------------------------------
#define TK 1024
#define TK4 (TK / 4)          // 256 float4 per batch row per chunk
#define ROWS_PER_WARP_1 4
#define ROWS_PER_BLOCK_1 (ROWS_PER_WARP_1 * 8)   // 32

__global__ __launch_bounds__(256, 2)
void rnn_i2h_kernel(const float* __restrict__ x,
                    const float* __restrict__ h0,
                    const float* __restrict__ W,      // [HIDDEN_SIZE, KDIM]
                    const float* __restrict__ bias)   // [HIDDEN_SIZE]
{
    __shared__ float4 s_in[BATCH][TK4];   // 32 KB

    const int tid  = threadIdx.x;
    const int lane = tid & 31;
    const int warp = tid >> 5;
    const int row0 = blockIdx.x * ROWS_PER_BLOCK_1 + warp * ROWS_PER_WARP_1;

    float acc[ROWS_PER_WARP_1][BATCH];
    #pragma unroll
    for (int r = 0; r < ROWS_PER_WARP_1; r++)
        #pragma unroll
        for (int b = 0; b < BATCH; b++)
            acc[r][b] = 0.0f;

    const int NCHUNK = KDIM / TK;          // 16
    const int XCHUNK = INPUT_SIZE / TK;    // 8

    for (int c = 0; c < NCHUNK; ++c) {
        // --- stage input chunk into shared: 8 batches x 1024 floats -------
        const float* src = (c < XCHUNK) ? (x + c * TK)
                                        : (h0 + (c - XCHUNK) * TK);
        #pragma unroll
        for (int t = 0; t < (BATCH * TK4) / 256; ++t) {   // 8 float4 per thread
            int f  = tid + t * 256;
            int b  = f >> 8;            // / TK4
            int k4 = f & (TK4 - 1);
            s_in[b][k4] = ((const float4*)(src + (size_t)b * INPUT_SIZE))[k4];
        }
        __syncthreads();

        // --- compute: each warp does 4 weight rows over this chunk --------
        const float* Wc = W + (size_t)c * TK;
        #pragma unroll 2
        for (int i = 0; i < TK4 / 32; ++i) {              // 8 iters
            const int k4 = i * 32 + lane;
            float4 w[ROWS_PER_WARP_1];
            #pragma unroll
            for (int r = 0; r < ROWS_PER_WARP_1; r++)
                w[r] = ((const float4*)(Wc + (size_t)(row0 + r) * KDIM))[k4];

            #pragma unroll
            for (int b = 0; b < BATCH; b++) {
                float4 v = s_in[b][k4];
                #pragma unroll
                for (int r = 0; r < ROWS_PER_WARP_1; r++) {
                    acc[r][b] = fmaf(w[r].x, v.x, acc[r][b]);
                    acc[r][b] = fmaf(w[r].y, v.y, acc[r][b]);
                    acc[r][b] = fmaf(w[r].z, v.z, acc[r][b]);
                    acc[r][b] = fmaf(w[r].w, v.w, acc[r][b]);
                }
            }
        }
        __syncthreads();
    }

    // --- warp-level butterfly reduction (each sum ends on all lanes) ------
    #pragma unroll
    for (int r = 0; r < ROWS_PER_WARP_1; r++)
        #pragma unroll
        for (int b = 0; b < BATCH; b++)
            #pragma unroll
            for (int off = 16; off > 0; off >>= 1)
                acc[r][b] += __shfl_xor_sync(0xffffffffu, acc[r][b], off);

    #pragma unroll
    for (int r = 0; r < ROWS_PER_WARP_1; r++) {
        const int row = row0 + r;
        const float bv = __ldg(bias + row);
        #pragma unroll
        for (int b = 0; b < BATCH; b++)
            if (lane == b)
                g_hidden[b * HIDDEN_SIZE + row] = tanhf(acc[r][b] + bv);
    }
}

// ---------------------------------------------------------------------------
// Kernel 2: out[b,o] = hidden[b,:]·W2[o,:] + bias2[o]
// Block: 256 threads, 2 rows per warp -> 16 rows per block -> 128 blocks.
// ---------------------------------------------------------------------------
#define ROWS_PER_WARP_2 2
#define ROWS_PER_BLOCK_2 (ROWS_PER_WARP_2 * 8)   // 16

__global__ __launch_bounds__(256, 2)
void rnn_h2o_kernel(const float* __restrict__ W2,     // [OUTPUT_SIZE, HIDDEN_SIZE]
                    const float* __restrict__ bias2,  // [OUTPUT_SIZE]
                    float* __restrict__ out)          // [BATCH, OUTPUT_SIZE]
{
    __shared__ float4 s_in[BATCH][TK4];   // 32 KB

    const int tid  = threadIdx.x;
    const int lane = tid & 31;
    const int warp = tid >> 5;
    const int row0 = blockIdx.x * ROWS_PER_BLOCK_2 + warp * ROWS_PER_WARP_2;

    float acc[ROWS_PER_WARP_2][BATCH];
    #pragma unroll
    for (int r = 0; r < ROWS_PER_WARP_2; r++)
        #pragma unroll
        for (int b = 0; b < BATCH; b++)
            acc[r][b] = 0.0f;

    const int NCHUNK = HIDDEN_SIZE / TK;   // 8

    for (int c = 0; c < NCHUNK; ++c) {
        const float* src = g_hidden + c * TK;
        #pragma unroll
        for (int t = 0; t < (BATCH * TK4) / 256; ++t) {
            int f  = tid + t * 256;
            int b  = f >> 8;
            int k4 = f & (TK4 - 1);
            s_in[b][k4] = ((const float4*)(src + (size_t)b * HIDDEN_SIZE))[k4];
        }
        __syncthreads();

        const float* Wc = W2 + (size_t)c * TK;
        #pragma unroll 2
        for (int i = 0; i < TK4 / 32; ++i) {
            const int k4 = i * 32 + lane;
            float4 w[ROWS_PER_WARP_2];
            #pragma unroll
            for (int r = 0; r < ROWS_PER_WARP_2; r++)
                w[r] = ((const float4*)(Wc + (size_t)(row0 + r) * HIDDEN_SIZE))[k4];

            #pragma unroll
            for (int b = 0; b < BATCH; b++) {
                float4 v = s_in[b][k4];
                #pragma unroll
                for (int r = 0; r < ROWS_PER_WARP_2; r++) {
                    acc[r][b] = fmaf(w[r].x, v.x, acc[r][b]);
                    acc[r][b] = fmaf(w[r].y, v.y, acc[r][b]);
                    acc[r][b] = fmaf(w[r].z, v.z, acc[r][b]);
                    acc[r][b] = fmaf(w[r].w, v.w, acc[r][b]);
                }
            }
        }
        __syncthreads();
    }

    #pragma unroll
    for (int r = 0; r < ROWS_PER_WARP_2; r++)
        #pragma unroll
        for (int b = 0; b < BATCH; b++)
            #pragma unroll
            for (int off = 16; off > 0; off >>= 1)
                acc[r][b] += __shfl_xor_sync(0xffffffffu, acc[r][b], off);

    #pragma unroll
    for (int r = 0; r < ROWS_PER_WARP_2; r++) {
        const int row = row0 + r;
        const float bv = __ldg(bias2 + row);
        #pragma unroll
        for (int b = 0; b < BATCH; b++)
            if (lane == b)
                out[b * OUTPUT_SIZE + row] = acc[r][b] + bv;
    }
}

// ---------------------------------------------------------------------------
// Launch: two dependent kernels on the default stream (graph-capturable).
// Inputs (metadata order): x, initial_hidden, i2h_weight, i2h_bias,
//                          h2o_weight, h2o_bias
// ---------------------------------------------------------------------------
extern "C" void kernel_launch(void* const* d_in, const int* in_sizes, int n_in,
                              void* d_out, int out_size) {
    const float* x    = (const float*)d_in[0];
    const float* h0   = (const float*)d_in[1];
    const float* W1   = (const float*)d_in[2];
    const float* b1   = (const float*)d_in[3];
    const float* W2   = (const float*)d_in[4];
    const float* b2   = (const float*)d_in[5];
    float* out        = (float*)d_out;

    rnn_i2h_kernel<<<HIDDEN_SIZE / ROWS_PER_BLOCK_1, 256>>>(x, h0, W1, b1);
    rnn_h2o_kernel<<<OUTPUT_SIZE / ROWS_PER_BLOCK_2, 256>>>(W2, b2, out);
}

// round 2
// speedup vs baseline: 1.1162x; 1.1162x over previous
#include <cuda_runtime.h>

#define BATCH 8
#define INPUT_SIZE 8192
#define HIDDEN_SIZE 8192
#define OUTPUT_SIZE 2048
#define KDIM (INPUT_SIZE + HIDDEN_SIZE)   // 16384

// Intermediate hidden activations (8 x 8192 fp32 = 256 KB).
__device__ float g_hidden[BATCH * HIDDEN_SIZE];
// Partial sums for the K-split h2o GEMV: [split][batch][out]
__device__ float g_part[2][BATCH][OUTPUT_SIZE];

// ---------------------------------------------------------------------------
// cp.async helpers (16B variant)
// ---------------------------------------------------------------------------
__device__ __forceinline__ void cp_async16(void* smem_dst, const void* gmem_src) {
    unsigned s = (unsigned)__cvta_generic_to_shared(smem_dst);
    asm volatile("cp.async.cg.shared.global [%0], [%1], 16;\n" :: "r"(s), "l"(gmem_src));
}
__device__ __forceinline__ void cp_commit()  { asm volatile("cp.async.commit_group;\n"); }
__device__ __forceinline__ void cp_wait1()   { asm volatile("cp.async.wait_group 1;\n"); }
__device__ __forceinline__ void cp_wait0()   { asm volatile("cp.async.wait_group 0;\n"); }

#define TK  512
#define TK4 (TK / 4)    // 128 float4 per batch per chunk

// ===========================================================================
// Kernel 1: hidden[b,h] = tanh( x[b,:]·W[h,0:8192] + h0[b,:]·W[h,8192:] + b1[h] )
// 256 threads (8 warps), 4 rows/warp -> 32 rows/block, grid = 256.
// K pipelined in 32 chunks of 512 floats, cp.async double buffered.
// ===========================================================================
#define R1 4
#define ROWS_PER_BLOCK_1 (R1 * 8)   // 32

__global__ __launch_bounds__(256, 2)
void rnn_i2h_kernel(const float* __restrict__ x,
                    const float* __restrict__ h0,
                    const float* __restrict__ W,      // [HIDDEN_SIZE, KDIM]
                    const float* __restrict__ bias)
{
    __shared__ float4 s_in[2][BATCH][TK4];   // 2 x 16 KB

    const int tid  = threadIdx.x;
    const int lane = tid & 31;
    const int warp = tid >> 5;
    const int row0 = blockIdx.x * ROWS_PER_BLOCK_1 + warp * R1;

    const int NCHUNK = KDIM / TK;          // 32
    const int XCHUNK = INPUT_SIZE / TK;    // 16

    float acc[R1][BATCH];
    #pragma unroll
    for (int r = 0; r < R1; r++)
        #pragma unroll
        for (int b = 0; b < BATCH; b++)
            acc[r][b] = 0.0f;

    // Row base pointers
    const float* Wrow[R1];
    #pragma unroll
    for (int r = 0; r < R1; r++)
        Wrow[r] = W + (size_t)(row0 + r) * KDIM;

    // ---- stage(chunk c into buffer buf): 8 batches x 512 floats = 16 KB ---
    // 1024 float4 total -> 4 cp.async per thread
    auto stage = [&](int c, int buf) {
        const float* src = (c < XCHUNK) ? (x + c * TK)
                                        : (h0 + (c - XCHUNK) * TK);
        #pragma unroll
        for (int t = 0; t < 4; ++t) {
            int f  = tid + t * 256;
            int b  = f >> 7;            // / TK4 (=128)
            int k4 = f & (TK4 - 1);
            cp_async16(&s_in[buf][b][k4],
                       (const float4*)(src + (size_t)b * INPUT_SIZE) + k4);
        }
        cp_commit();
    };

    stage(0, 0);

    for (int c = 0; c < NCHUNK; ++c) {
        const int buf = c & 1;
        __syncthreads();                     // buffer (c+1)&1 is free now
        if (c + 1 < NCHUNK) { stage(c + 1, buf ^ 1); cp_wait1(); }
        else                { cp_wait0(); }
        __syncthreads();                     // chunk c visible to all warps

        const float* Wc0 = Wrow[0] + (size_t)c * TK;
        const float* Wc1 = Wrow[1] + (size_t)c * TK;
        const float* Wc2 = Wrow[2] + (size_t)c * TK;
        const float* Wc3 = Wrow[3] + (size_t)c * TK;

        #pragma unroll
        for (int i = 0; i < TK4 / 32; ++i) {          // 4 iterations
            const int k4 = i * 32 + lane;
            float4 w0 = __ldcs((const float4*)Wc0 + k4);
            float4 w1 = __ldcs((const float4*)Wc1 + k4);
            float4 w2 = __ldcs((const float4*)Wc2 + k4);
            float4 w3 = __ldcs((const float4*)Wc3 + k4);

            #pragma unroll
            for (int b = 0; b < BATCH; b++) {
                float4 v = s_in[buf][b][k4];
                acc[0][b] = fmaf(w0.x, v.x, acc[0][b]);
                acc[0][b] = fmaf(w0.y, v.y, acc[0][b]);
                acc[0][b] = fmaf(w0.z, v.z, acc[0][b]);
                acc[0][b] = fmaf(w0.w, v.w, acc[0][b]);
                acc[1][b] = fmaf(w1.x, v.x, acc[1][b]);
                acc[1][b] = fmaf(w1.y, v.y, acc[1][b]);
                acc[1][b] = fmaf(w1.z, v.z, acc[1][b]);
                acc[1][b] = fmaf(w1.w, v.w, acc[1][b]);
                acc[2][b] = fmaf(w2.x, v.x, acc[2][b]);
                acc[2][b] = fmaf(w2.y, v.y, acc[2][b]);
                acc[2][b] = fmaf(w2.z, v.z, acc[2][b]);
                acc[2][b] = fmaf(w2.w, v.w, acc[2][b]);
                acc[3][b] = fmaf(w3.x, v.x, acc[3][b]);
                acc[3][b] = fmaf(w3.y, v.y, acc[3][b]);
                acc[3][b] = fmaf(w3.z, v.z, acc[3][b]);
                acc[3][b] = fmaf(w3.w, v.w, acc[3][b]);
            }
        }
    }

    // warp butterfly reduction
    #pragma unroll
    for (int r = 0; r < R1; r++)
        #pragma unroll
        for (int b = 0; b < BATCH; b++)
            #pragma unroll
            for (int off = 16; off > 0; off >>= 1)
                acc[r][b] += __shfl_xor_sync(0xffffffffu, acc[r][b], off);

    #pragma unroll
    for (int r = 0; r < R1; r++) {
        const int row = row0 + r;
        const float bv = __ldg(bias + row);
        #pragma unroll
        for (int b = 0; b < BATCH; b++)
            if (lane == b)
                g_hidden[b * HIDDEN_SIZE + row] = tanhf(acc[r][b] + bv);
    }
}

// ===========================================================================
// Kernel 2: K-split GEMV.  part[s][b,o] = hidden[b, s*4096:(s+1)*4096]·W2[o, ...]
// 256 threads, 2 rows/warp -> 16 rows/block, grid = 128 tiles x 2 splits = 256.
// ===========================================================================
#define R2 2
#define ROWS_PER_BLOCK_2 (R2 * 8)   // 16
#define KSPLIT 2
#define KHALF (HIDDEN_SIZE / KSPLIT)   // 4096

__global__ __launch_bounds__(256, 2)
void rnn_h2o_kernel(const float* __restrict__ W2)   // [OUTPUT_SIZE, HIDDEN_SIZE]
{
    __shared__ float4 s_in[2][BATCH][TK4];   // 2 x 16 KB

    const int tid  = threadIdx.x;
    const int lane = tid & 31;
    const int warp = tid >> 5;
    const int tile = blockIdx.x & 127;          // 128 row tiles
    const int half = blockIdx.x >> 7;           // 0 or 1
    const int row0 = tile * ROWS_PER_BLOCK_2 + warp * R2;
    const int kbase = half * KHALF;

    const int NCHUNK = KHALF / TK;   // 8

    float acc[R2][BATCH];
    #pragma unroll
    for (int r = 0; r < R2; r++)
        #pragma unroll
        for (int b = 0; b < BATCH; b++)
            acc[r][b] = 0.0f;

    auto stage = [&](int c, int buf) {
        const float* src = g_hidden + kbase + c * TK;
        #pragma unroll
        for (int t = 0; t < 4; ++t) {
            int f  = tid + t * 256;
            int b  = f >> 7;
            int k4 = f & (TK4 - 1);
            cp_async16(&s_in[buf][b][k4],
                       (const float4*)(src + (size_t)b * HIDDEN_SIZE) + k4);
        }
        cp_commit();
    };

    stage(0, 0);

    const float* W0 = W2 + (size_t)(row0 + 0) * HIDDEN_SIZE + kbase;
    const float* W1 = W2 + (size_t)(row0 + 1) * HIDDEN_SIZE + kbase;

    for (int c = 0; c < NCHUNK; ++c) {
        const int buf = c & 1;
        __syncthreads();
        if (c + 1 < NCHUNK) { stage(c + 1, buf ^ 1); cp_wait1(); }
        else                { cp_wait0(); }
        __syncthreads();

        const float* Wc0 = W0 + (size_t)c * TK;
        const float* Wc1 = W1 + (size_t)c * TK;

        #pragma unroll
        for (int i = 0; i < TK4 / 32; ++i) {
            const int k4 = i * 32 + lane;
            float4 w0 = __ldcs((const float4*)Wc0 + k4);
            float4 w1 = __ldcs((const float4*)Wc1 + k4);

            #pragma unroll
            for (int b = 0; b < BATCH; b++) {
                float4 v = s_in[buf][b][k4];
                acc[0][b] = fmaf(w0.x, v.x, acc[0][b]);
                acc[0][b] = fmaf(w0.y, v.y, acc[0][b]);
                acc[0][b] = fmaf(w0.z, v.z, acc[0][b]);
                acc[0][b] = fmaf(w0.w, v.w, acc[0][b]);
                acc[1][b] = fmaf(w1.x, v.x, acc[1][b]);
                acc[1][b] = fmaf(w1.y, v.y, acc[1][b]);
                acc[1][b] = fmaf(w1.z, v.z, acc[1][b]);
                acc[1][b] = fmaf(w1.w, v.w, acc[1][b]);
            }
        }
    }

    #pragma unroll
    for (int r = 0; r < R2; r++)
        #pragma unroll
        for (int b = 0; b < BATCH; b++)
            #pragma unroll
            for (int off = 16; off > 0; off >>= 1)
                acc[r][b] += __shfl_xor_sync(0xffffffffu, acc[r][b], off);

    #pragma unroll
    for (int r = 0; r < R2; r++) {
        const int row = row0 + r;
        #pragma unroll
        for (int b = 0; b < BATCH; b++)
            if (lane == b)
                g_part[half][b][row] = acc[r][b];
    }
}

// ===========================================================================
// Kernel 3: out[b,o] = part[0][b,o] + part[1][b,o] + bias2[o]
// ===========================================================================
__global__ void rnn_reduce_kernel(const float* __restrict__ bias2,
                                  float* __restrict__ out)
{
    int idx = blockIdx.x * blockDim.x + threadIdx.x;   // 16384 total
    int b = idx >> 11;               // / OUTPUT_SIZE
    int o = idx & (OUTPUT_SIZE - 1);
    out[idx] = g_part[0][b][o] + g_part[1][b][o] + __ldg(bias2 + o);
}

// ---------------------------------------------------------------------------
// Inputs (metadata order): x, initial_hidden, i2h_weight, i2h_bias,
//                          h2o_weight, h2o_bias
// ---------------------------------------------------------------------------
extern "C" void kernel_launch(void* const* d_in, const int* in_sizes, int n_in,
                              void* d_out, int out_size) {
    const float* x    = (const float*)d_in[0];
    const float* h0   = (const float*)d_in[1];
    const float* W1   = (const float*)d_in[2];
    const float* b1   = (const float*)d_in[3];
    const float* W2   = (const float*)d_in[4];
    const float* b2   = (const float*)d_in[5];
    float* out        = (float*)d_out;

    rnn_i2h_kernel<<<HIDDEN_SIZE / ROWS_PER_BLOCK_1, 256>>>(x, h0, W1, b1);
    rnn_h2o_kernel<<<(OUTPUT_SIZE / ROWS_PER_BLOCK_2) * KSPLIT, 256>>>(W2);
    rnn_reduce_kernel<<<(BATCH * OUTPUT_SIZE) / 256, 256>>>(b2, out);
}